// round 5
// baseline (speedup 1.0000x reference)
#include <cuda_runtime.h>
#include <cuda_bf16.h>
#include <cstdint>
#include <cstddef>

// ---------------- Problem constants ----------------
#define PP 20000   // total proxies
#define CC 1000    // num classes
#define DD 512     // embedding dim
#define BB 4096    // eval batch

// ---------------- Device scratch (no allocs allowed) ----------------
__device__ float g_dataN[(size_t)BB * DD];        // 8 MB   normalized data
__device__ float g_w1N[(size_t)PP * DD];          // 40 MB  normalized w1
__device__ float g_xT[(size_t)BB * PP];           // 327 MB x transposed: [b][p]
__device__ float g_thr[BB];
__device__ int   g_seg32[PP];

// ---------------- f32x2 packed helpers (sm_103a) ----------------
__device__ __forceinline__ unsigned long long pk2(float lo, float hi) {
    unsigned long long r;
    asm("mov.b64 %0, {%1, %2};" : "=l"(r) : "r"(__float_as_uint(lo)), "r"(__float_as_uint(hi)));
    return r;
}
__device__ __forceinline__ unsigned long long fma2(unsigned long long a,
                                                   unsigned long long b,
                                                   unsigned long long c) {
    unsigned long long d;
    asm("fma.rn.f32x2 %0, %1, %2, %3;" : "=l"(d) : "l"(a), "l"(b), "l"(c));
    return d;
}
__device__ __forceinline__ void upk2(unsigned long long v, float& lo, float& hi) {
    unsigned int a, b;
    asm("mov.b64 {%0, %1}, %2;" : "=r"(a), "=r"(b) : "l"(v));
    lo = __uint_as_float(a);
    hi = __uint_as_float(b);
}

// Order-preserving float<->uint key (for atomic max/min on floats)
__device__ __forceinline__ unsigned int f2key(float f) {
    unsigned int u = __float_as_uint(f);
    return (u & 0x80000000u) ? ~u : (u | 0x80000000u);
}
__device__ __forceinline__ float key2f(unsigned int k) {
    unsigned int u = (k & 0x80000000u) ? (k & 0x7FFFFFFFu) : ~k;
    return __uint_as_float(u);
}

// ---------------- 1) row L2 normalize (D=512, 128 threads/row) ----------------
__global__ void l2norm_rows_kernel(const float* __restrict__ in, float* __restrict__ out) {
    int row = blockIdx.x;
    int tid = threadIdx.x;  // 128
    const float4* ip = reinterpret_cast<const float4*>(in + (size_t)row * DD);
    float4 v = ip[tid];
    float ss = v.x * v.x + v.y * v.y + v.z * v.z + v.w * v.w;
#pragma unroll
    for (int o = 16; o > 0; o >>= 1) ss += __shfl_xor_sync(0xffffffffu, ss, o);
    __shared__ float wsum[4];
    if ((tid & 31) == 0) wsum[tid >> 5] = ss;
    __syncthreads();
    float total = wsum[0] + wsum[1] + wsum[2] + wsum[3];
    float m = fmaxf(sqrtf(total), 1e-12f);
    float4 o4;
    o4.x = v.x / m; o4.y = v.y / m; o4.z = v.z / m; o4.w = v.w / m;
    reinterpret_cast<float4*>(out + (size_t)row * DD)[tid] = o4;
}

// ---------------- segment id cast: dtype-robust (int32 OR int64 buffer) ------
// JAX with x64 disabled silently makes jnp.int64 -> int32, so the buffer may be
// either 20000 x int32 or 20000 x int64. Discriminator (in-bounds for BOTH):
//   word[19999] as int32:
//     int32 layout -> ids[19999] == 999 (nonzero: ids sorted, every class hit)
//     int64 layout -> high word of ids[9999] == 0 (ids in [0,999])
__global__ void seg_cast_kernel(const void* __restrict__ s) {
    const int* w = (const int*)s;
    bool is64 = (w[19999] == 0);
    int i = blockIdx.x * 256 + threadIdx.x;
    if (i < PP) {
        int v;
        if (is64) v = (int)((const long long*)s)[i];
        else      v = w[i];
        // clamp defensively: garbage id must never produce OOB smem atomics
        g_seg32[i] = min(max(v, 0), CC - 1);
    }
}

// ---------------- 2) fp32 GEMM: xT[b][p] = dot(dataN[b,:], w1N[p,:]) ----------
// Tiles: BM=128 (b), BN=128 (p), BK=16, 256 threads, 8x8 per thread, FFMA2 inner.
__global__ __launch_bounds__(256, 2) void sgemm_nt_kernel() {
    __shared__ float As[16][128];
    __shared__ float Bs[16][128];
    int tid = threadIdx.x;
    int m0 = blockIdx.y * 128;   // b tile
    int n0 = blockIdx.x * 128;   // p tile
    int tx = tid & 15, ty = tid >> 4;

    unsigned long long acc[8][4];
#pragma unroll
    for (int i = 0; i < 8; i++)
#pragma unroll
        for (int j = 0; j < 4; j++) acc[i][j] = 0ULL;

    for (int k0 = 0; k0 < DD; k0 += 16) {
#pragma unroll
        for (int l = 0; l < 2; ++l) {
            int f = tid + l * 256;        // 512 float4 loads per tile
            int row = f >> 2;
            int c4 = (f & 3) << 2;
            float4 av = *reinterpret_cast<const float4*>(
                &g_dataN[(size_t)(m0 + row) * DD + k0 + c4]);
            As[c4 + 0][row] = av.x; As[c4 + 1][row] = av.y;
            As[c4 + 2][row] = av.z; As[c4 + 3][row] = av.w;
            int gn = n0 + row;
            float4 bv = make_float4(0.f, 0.f, 0.f, 0.f);
            if (gn < PP)
                bv = *reinterpret_cast<const float4*>(&g_w1N[(size_t)gn * DD + k0 + c4]);
            Bs[c4 + 0][row] = bv.x; Bs[c4 + 1][row] = bv.y;
            Bs[c4 + 2][row] = bv.z; Bs[c4 + 3][row] = bv.w;
        }
        __syncthreads();
#pragma unroll
        for (int k = 0; k < 16; ++k) {
            float4 a0 = *reinterpret_cast<const float4*>(&As[k][ty * 8]);
            float4 a1 = *reinterpret_cast<const float4*>(&As[k][ty * 8 + 4]);
            float4 b0 = *reinterpret_cast<const float4*>(&Bs[k][tx * 8]);
            float4 b1 = *reinterpret_cast<const float4*>(&Bs[k][tx * 8 + 4]);
            unsigned long long b2[4] = {
                pk2(b0.x, b0.y), pk2(b0.z, b0.w), pk2(b1.x, b1.y), pk2(b1.z, b1.w)};
            float aa[8] = {a0.x, a0.y, a0.z, a0.w, a1.x, a1.y, a1.z, a1.w};
#pragma unroll
            for (int i = 0; i < 8; i++) {
                unsigned long long ad = pk2(aa[i], aa[i]);
#pragma unroll
                for (int j = 0; j < 4; j++) acc[i][j] = fma2(ad, b2[j], acc[i][j]);
            }
        }
        __syncthreads();
    }

#pragma unroll
    for (int i = 0; i < 8; i++) {
        int row = m0 + ty * 8 + i;  // b index, always < BB
        float v[8];
#pragma unroll
        for (int j = 0; j < 4; j++) { upk2(acc[i][j], v[2 * j], v[2 * j + 1]); }
        int colb = n0 + tx * 8;
        size_t base = (size_t)row * PP;
        if (colb < PP)                      // PP % 8 == 0, so float4 stores stay in-bounds
            *reinterpret_cast<float4*>(&g_xT[base + colb]) =
                make_float4(v[0], v[1], v[2], v[3]);
        if (colb + 4 < PP)
            *reinterpret_cast<float4*>(&g_xT[base + colb + 4]) =
                make_float4(v[4], v[5], v[6], v[7]);
    }
}

// ---------------- 3) per-column 0.95-quantile threshold ----------------
// One block per column b. Column (20000 floats) staged in smem; histogram
// selects exact rank-1000 / rank-1001 (largest), then jnp.quantile 'linear'.
#define QBINS 1024
#define QCAP  1024
#define QSMEM ((PP + QCAP + QBINS) * 4)

__global__ __launch_bounds__(512) void quantile_kernel() {
    extern __shared__ float sm[];
    float* col = sm;                       // PP
    float* cand = sm + PP;                 // QCAP
    int* hist = (int*)(cand + QCAP);       // QBINS
    __shared__ int s_t, s_cnt, s_rankAbove;
    __shared__ unsigned int s_minAbove;
    __shared__ int gsum[32];

    int b = blockIdx.x, tid = threadIdx.x, nt = blockDim.x;
    const float4* src4 = reinterpret_cast<const float4*>(g_xT + (size_t)b * PP);
    float4* col4 = reinterpret_cast<float4*>(col);
    for (int i = tid; i < PP / 4; i += nt) col4[i] = src4[i];
    for (int i = tid; i < QBINS; i += nt) hist[i] = 0;
    if (tid == 0) { s_cnt = 0; s_minAbove = 0xFFFFFFFFu; }
    __syncthreads();

    const float lo = -1.001f;
    const float scale = (float)QBINS / 2.002f;   // range [-1.001, 1.001]
    for (int i = tid; i < PP; i += nt) {
        int bin = (int)((col[i] - lo) * scale);
        bin = min(max(bin, 0), QBINS - 1);
        atomicAdd(&hist[bin], 1);
    }
    __syncthreads();

    // two-level suffix search for bin t: largest t with count(bin >= t) >= 1001
    if (tid < 32) {
        int s = 0;
#pragma unroll 8
        for (int j = 0; j < 32; j++) s += hist[tid * 32 + j];
        gsum[tid] = s;
    }
    __syncthreads();
    if (tid == 0) {
        int run = 0, gi = 31;
        for (; gi >= 0; --gi) { run += gsum[gi]; if (run >= 1001) break; }
        int above = run - gsum[gi];
        int suf = above, j = 31;
        for (; j >= 0; --j) { suf += hist[gi * 32 + j]; if (suf >= 1001) break; }
        s_t = gi * 32 + j;
        s_rankAbove = suf - hist[gi * 32 + j];   // count with bin > t  (<= 1000)
    }
    __syncthreads();
    int t = s_t;

    // gather bin==t candidates; track min of values with bin>t
    for (int i = tid; i < PP; i += nt) {
        float v = col[i];
        int bin = (int)((v - lo) * scale);
        bin = min(max(bin, 0), QBINS - 1);
        if (bin == t) {
            int idx = atomicAdd(&s_cnt, 1);
            if (idx < QCAP) cand[idx] = v;
        } else if (bin > t) {
            atomicMin(&s_minAbove, f2key(v));
        }
    }
    __syncthreads();
    int m = min(s_cnt, QCAP);
    for (int i = tid; i < QCAP; i += nt)
        if (i >= m) cand[i] = -__int_as_float(0x7f800000);  // -inf pad
    __syncthreads();

    // bitonic sort descending over QCAP
    for (int kk = 2; kk <= QCAP; kk <<= 1) {
        for (int jj = kk >> 1; jj > 0; jj >>= 1) {
            for (int i = tid; i < QCAP; i += nt) {
                int ixj = i ^ jj;
                if (ixj > i) {
                    float a = cand[i], c = cand[ixj];
                    bool up = ((i & kk) == 0);  // descending blocks
                    if (up ? (a < c) : (a > c)) { cand[i] = c; cand[ixj] = a; }
                }
            }
            __syncthreads();
        }
    }

    if (tid == 0) {
        int R1 = s_rankAbove;  // values strictly above bin t (ranks 1..R1)
        // global rank-k largest (k>R1) = cand[k-R1-1]
        float v1000 = (R1 >= 1000) ? key2f(s_minAbove) : cand[999 - R1];
        float v1001 = cand[1000 - R1];
        // replicate jnp.quantile 'linear' in f32:
        float qq = __fmul_rn(0.95f, (float)(PP - 1));   // 0.95*(n-1)
        float fl = floorf(qq);
        float w_hi = __fadd_rn(qq, -fl);                 // q - low
        float w_lo = __fadd_rn(fl + 1.0f, -qq);          // high - q
        float thr = __fadd_rn(__fmul_rn(v1001, w_lo), __fmul_rn(v1000, w_hi));
        g_thr[b] = thr;
    }
}

// ---------------- 4) threshold + ragged segment max ----------------
// 8 columns per block; smem atomicMax on ordered keys; coalesced output.
__global__ __launch_bounds__(256) void segmax_kernel(float* __restrict__ out) {
    __shared__ unsigned int keys[8 * CC];
    int b0 = blockIdx.x * 8;
    int tid = threadIdx.x;
    for (int i = tid; i < 8 * CC; i += 256) keys[i] = 0u;  // key(0.0f), floor value
    __syncthreads();

    float th[8];
#pragma unroll
    for (int cc = 0; cc < 8; ++cc) th[cc] = g_thr[b0 + cc];

    for (int p = tid; p < PP; p += 256) {
        int c = g_seg32[p];
#pragma unroll
        for (int cc = 0; cc < 8; ++cc) {
            float v = g_xT[(size_t)(b0 + cc) * PP + p];
            v = (v < th[cc]) ? 0.0f : v;
            atomicMax(&keys[cc * CC + c], f2key(v));
        }
    }
    __syncthreads();

    for (int i = tid; i < 8 * CC; i += 256) {
        int c = i >> 3, cc = i & 7;
        out[(size_t)c * BB + b0 + cc] = key2f(keys[cc * CC + c]);
    }
}

// ---------------- launch ----------------
extern "C" void kernel_launch(void* const* d_in, const int* in_sizes, int n_in,
                              void* d_out, int out_size) {
    const float* data = nullptr;
    const float* w1 = nullptr;
    const void* segs = nullptr;
    for (int i = 0; i < n_in; ++i) {
        long long sz = in_sizes[i];
        if (sz == (long long)BB * DD) data = (const float*)d_in[i];
        else if (sz == (long long)PP * DD) w1 = (const float*)d_in[i];
        else if (sz == (long long)PP) segs = d_in[i];
    }
    if (!data) data = (const float*)d_in[0];
    if (!w1) w1 = (const float*)d_in[1];
    if (!segs) segs = d_in[2];
    float* out = (float*)d_out;

    float* dataN;  cudaGetSymbolAddress((void**)&dataN, g_dataN);
    float* w1N;    cudaGetSymbolAddress((void**)&w1N, g_w1N);

    l2norm_rows_kernel<<<BB, 128>>>(data, dataN);
    l2norm_rows_kernel<<<PP, 128>>>(w1, w1N);
    seg_cast_kernel<<<(PP + 255) / 256, 256>>>(segs);

    dim3 ggrid((PP + 127) / 128, BB / 128);
    sgemm_nt_kernel<<<ggrid, 256>>>();

    cudaFuncSetAttribute(quantile_kernel,
                         cudaFuncAttributeMaxDynamicSharedMemorySize, QSMEM);
    quantile_kernel<<<BB, 512, QSMEM>>>();

    segmax_kernel<<<BB / 8, 256>>>(out);
}

// round 7
// speedup vs baseline: 1.3645x; 1.3645x over previous
#include <cuda_runtime.h>
#include <cuda_bf16.h>
#include <cstdint>
#include <cstddef>

// ---------------- Problem constants ----------------
#define PP 20000   // total proxies
#define CC 1000    // num classes
#define DD 512     // embedding dim
#define BB 4096    // eval batch
#define PPAD 20224 // 79 * 256 padded proxies
#define NTILES 79  // p tiles of 256
#define MTILES 32  // b tiles of 128
#define NSTAGES 48 // virtual K = 3*512, 32 floats per stage
#define STAGEB 49152   // per-buffer smem: A 16KB + B 32KB
#define GSMEM (2 * STAGEB)

// ---------------- Device scratch (no allocs allowed) ----------------
__device__ float g_xT[(size_t)BB * PP];          // 327 MB  x transposed [b][p]
__device__ float g_thr[BB];
__device__ int   g_seg32[PP];
__device__ float g_Af[2 * (size_t)BB * DD];      // data tf32 split terms h,m
__device__ float g_Bf[2 * (size_t)PPAD * DD];    // w1 tf32 split terms h,m (pad rows 0)

#define ASZB ((size_t)BB * DD * 4)               // bytes per A term
#define BSZB ((size_t)PPAD * DD * 4)             // bytes per B term

// ---------------- small helpers ----------------
__device__ __forceinline__ uint32_t smem_u32(const void* p) {
    uint32_t a;
    asm("{ .reg .u64 t; cvta.to.shared.u64 t, %1; cvt.u32.u64 %0, t; }"
        : "=r"(a) : "l"(p));
    return a;
}
__device__ __forceinline__ float tf32_rna(float x) {
    uint32_t u;
    asm("cvt.rna.tf32.f32 %0, %1;" : "=r"(u) : "f"(x));
    return __uint_as_float(u);
}
#define CP_ASYNC16(dst, src) \
    asm volatile("cp.async.cg.shared.global [%0], [%1], 16;" :: "r"(dst), "l"(src))
#define CP_COMMIT asm volatile("cp.async.commit_group;" ::: "memory")
#define CP_WAIT1  asm volatile("cp.async.wait_group 1;" ::: "memory")
#define CP_WAIT0  asm volatile("cp.async.wait_group 0;" ::: "memory")

#define MMA_TF32(c, a0, a1, a2, a3, b0, b1) \
    asm volatile( \
        "mma.sync.aligned.m16n8k8.row.col.f32.tf32.tf32.f32 " \
        "{%0,%1,%2,%3}, {%4,%5,%6,%7}, {%8,%9}, {%0,%1,%2,%3};" \
        : "+f"((c)[0]), "+f"((c)[1]), "+f"((c)[2]), "+f"((c)[3]) \
        : "r"(a0), "r"(a1), "r"(a2), "r"(a3), "r"(b0), "r"(b1))

// Order-preserving float<->uint key (for atomic max/min on floats)
__device__ __forceinline__ unsigned int f2key(float f) {
    unsigned int u = __float_as_uint(f);
    return (u & 0x80000000u) ? ~u : (u | 0x80000000u);
}
__device__ __forceinline__ float key2f(unsigned int k) {
    unsigned int u = (k & 0x80000000u) ? (k & 0x7FFFFFFFu) : ~k;
    return __uint_as_float(u);
}

// ---------------- 1) L2-normalize + 2-term tf32 split ----------------
// 128 threads/row. Terms: h at out[row], m at out + term_stride.
__global__ void norm_split_kernel(const float* __restrict__ in,
                                  float* __restrict__ out,
                                  size_t term_stride, int nvalid) {
    int row = blockIdx.x;
    int tid = threadIdx.x;  // 128
    float* hp = out + ((size_t)row << 9);
    float* mp = hp + term_stride;
    if (row >= nvalid) {  // zero-pad rows -> MMA contributes 0
        float4 z = make_float4(0.f, 0.f, 0.f, 0.f);
        reinterpret_cast<float4*>(hp)[tid] = z;
        reinterpret_cast<float4*>(mp)[tid] = z;
        return;
    }
    float4 v = reinterpret_cast<const float4*>(in + ((size_t)row << 9))[tid];
    float ss = v.x * v.x + v.y * v.y + v.z * v.z + v.w * v.w;
#pragma unroll
    for (int o = 16; o > 0; o >>= 1) ss += __shfl_xor_sync(0xffffffffu, ss, o);
    __shared__ float ws[4];
    if ((tid & 31) == 0) ws[tid >> 5] = ss;
    __syncthreads();
    float nrm = fmaxf(sqrtf(ws[0] + ws[1] + ws[2] + ws[3]), 1e-12f);
    float x[4] = {v.x / nrm, v.y / nrm, v.z / nrm, v.w / nrm};
    float4 h4, m4;
    float* hh = &h4.x; float* mm = &m4.x;
#pragma unroll
    for (int j = 0; j < 4; ++j) {
        float h = tf32_rna(x[j]);          // exact Dekker split (rounding error
        float m = tf32_rna(x[j] - h);      // of rna to 11-bit is fp32-exact)
        hh[j] = h; mm[j] = m;
    }
    reinterpret_cast<float4*>(hp)[tid] = h4;
    reinterpret_cast<float4*>(mp)[tid] = m4;
}

// ---------------- segment id cast: dtype-robust (int32 OR int64 buffer) ------
__global__ void seg_cast_kernel(const void* __restrict__ s) {
    const int* w = (const int*)s;
    bool is64 = (w[19999] == 0);
    int i = blockIdx.x * 256 + threadIdx.x;
    if (i < PP) {
        int v;
        if (is64) v = (int)((const long long*)s)[i];
        else      v = w[i];
        g_seg32[i] = min(max(v, 0), CC - 1);
    }
}

// ---------------- 2) 3xTF32 split GEMM on mma.sync (HMMA) ----------------
// Output tile [M=128 b x N=256 p]; virtual K = 1536 = segments [hh | hm | mh]
// as K-concat: A terms per segment {h,h,m}, B terms {h,m,h}.
// 256 threads = 8 warps, warp grid 2(m) x 4(n), warp tile 64x64,
// per warp 4 m16 tiles x 8 n8 tiles of m16n8k8.
// smem per stage: A 128x32 f32 (16KB, SW128-style swizzle) + B 256x32 f32 (32KB).
__global__ void __launch_bounds__(256, 1) tc_gemm_kernel() {
    extern __shared__ char smem[];
    const int tid = threadIdx.x;
    const int wid = tid >> 5, lane = tid & 31;
    const int wm = wid & 1, wn = wid >> 1;
    const int g = lane >> 2, tig = lane & 3;
    const int m0 = blockIdx.x * 128;
    const int n0 = blockIdx.y * 256;
    const uint32_t sbase = smem_u32(smem);

    float acc[4][8][4];
#pragma unroll
    for (int a = 0; a < 4; ++a)
#pragma unroll
        for (int b = 0; b < 8; ++b)
#pragma unroll
            for (int c = 0; c < 4; ++c) acc[a][b][c] = 0.f;

    // ---- stage loader (cp.async) ----
    auto load_stage = [&](int ks, int buf) {
        int seg = ks >> 4;                               // 0,1,2
        const char* abase = (const char*)g_Af + (seg == 2 ? ASZB : 0);
        const char* bbase = (const char*)g_Bf + (seg == 1 ? BSZB : 0);
        int kbyte = (ks & 15) << 7;                      // 128B per 32 floats
        uint32_t sbuf = sbase + buf * STAGEB;
#pragma unroll
        for (int i = 0; i < 12; ++i) {
            int idx = tid + (i << 8);
            if (idx < 1024) {                            // A: 128 rows x 8 chunks
                int r = idx >> 3, q = idx & 7;
                const char* src = abase + (size_t)(m0 + r) * 2048 + kbyte + (q << 4);
                uint32_t dst = sbuf + (r << 7) + ((q ^ (r & 7)) << 4);
                CP_ASYNC16(dst, src);
            } else {                                     // B: 256 rows x 8 chunks
                int j = idx - 1024;
                int r = j >> 3, q = j & 7;
                const char* src = bbase + (size_t)(n0 + r) * 2048 + kbyte + (q << 4);
                uint32_t dst = sbuf + 16384 + (r << 7) + ((q ^ (r & 7)) << 4);
                CP_ASYNC16(dst, src);
            }
        }
    };

    load_stage(0, 0);
    CP_COMMIT;

#pragma unroll 1
    for (int ks = 0; ks < NSTAGES; ++ks) {
        if (ks + 1 < NSTAGES) {
            load_stage(ks + 1, (ks + 1) & 1);
            CP_COMMIT;
            CP_WAIT1;
        } else {
            CP_WAIT0;
        }
        __syncthreads();

        const char* sA = smem + (ks & 1) * STAGEB;
        const char* sB = sA + 16384;
#pragma unroll
        for (int s = 0; s < 4; ++s) {
            int co0 = (((2 * s) ^ g) << 4) + tig * 4;    // k = s*8 + tig
            int co1 = co0 ^ 16;                          // k = s*8 + tig + 4
            uint32_t a[4][4];
#pragma unroll
            for (int mt = 0; mt < 4; ++mt) {
                int rb = (wm * 64 + mt * 16 + g) << 7;   // row * 128B
                a[mt][0] = *(const uint32_t*)(sA + rb + co0);
                a[mt][1] = *(const uint32_t*)(sA + rb + 1024 + co0);
                a[mt][2] = *(const uint32_t*)(sA + rb + co1);
                a[mt][3] = *(const uint32_t*)(sA + rb + 1024 + co1);
            }
#pragma unroll
            for (int nt = 0; nt < 8; ++nt) {
                int nb = (wn * 64 + nt * 8 + g) << 7;
                uint32_t b0 = *(const uint32_t*)(sB + nb + co0);
                uint32_t b1 = *(const uint32_t*)(sB + nb + co1);
#pragma unroll
                for (int mt = 0; mt < 4; ++mt)
                    MMA_TF32(acc[mt][nt], a[mt][0], a[mt][1], a[mt][2], a[mt][3], b0, b1);
            }
        }
        __syncthreads();
    }

    // ---- epilogue: direct fp32 stores (32B-coalesced per quad) ----
#pragma unroll
    for (int mt = 0; mt < 4; ++mt) {
        int row0 = m0 + wm * 64 + mt * 16 + g;
#pragma unroll
        for (int nt = 0; nt < 8; ++nt) {
            int p = n0 + wn * 64 + nt * 8 + tig * 2;
            if (p < PP) {
                *reinterpret_cast<float2*>(g_xT + (size_t)row0 * PP + p) =
                    make_float2(acc[mt][nt][0], acc[mt][nt][1]);
                *reinterpret_cast<float2*>(g_xT + (size_t)(row0 + 8) * PP + p) =
                    make_float2(acc[mt][nt][2], acc[mt][nt][3]);
            }
        }
    }
}

// ---------------- 3) per-column 0.95-quantile threshold (unchanged, R5) ------
#define QBINS 1024
#define QCAP  1024
#define QSMEM ((PP + QCAP + QBINS) * 4)

__global__ __launch_bounds__(512) void quantile_kernel() {
    extern __shared__ float sm[];
    float* col = sm;                       // PP
    float* cand = sm + PP;                 // QCAP
    int* hist = (int*)(cand + QCAP);       // QBINS
    __shared__ int s_t, s_cnt, s_rankAbove;
    __shared__ unsigned int s_minAbove;
    __shared__ int gsum[32];

    int b = blockIdx.x, tid = threadIdx.x, nt = blockDim.x;
    const float4* src4 = reinterpret_cast<const float4*>(g_xT + (size_t)b * PP);
    float4* col4 = reinterpret_cast<float4*>(col);
    for (int i = tid; i < PP / 4; i += nt) col4[i] = src4[i];
    for (int i = tid; i < QBINS; i += nt) hist[i] = 0;
    if (tid == 0) { s_cnt = 0; s_minAbove = 0xFFFFFFFFu; }
    __syncthreads();

    const float lo = -1.001f;
    const float scale = (float)QBINS / 2.002f;
    for (int i = tid; i < PP; i += nt) {
        int bin = (int)((col[i] - lo) * scale);
        bin = min(max(bin, 0), QBINS - 1);
        atomicAdd(&hist[bin], 1);
    }
    __syncthreads();

    if (tid < 32) {
        int s = 0;
#pragma unroll 8
        for (int j = 0; j < 32; j++) s += hist[tid * 32 + j];
        gsum[tid] = s;
    }
    __syncthreads();
    if (tid == 0) {
        int run = 0, gi = 31;
        for (; gi >= 0; --gi) { run += gsum[gi]; if (run >= 1001) break; }
        int above = run - gsum[gi];
        int suf = above, j = 31;
        for (; j >= 0; --j) { suf += hist[gi * 32 + j]; if (suf >= 1001) break; }
        s_t = gi * 32 + j;
        s_rankAbove = suf - hist[gi * 32 + j];
    }
    __syncthreads();
    int t = s_t;

    for (int i = tid; i < PP; i += nt) {
        float v = col[i];
        int bin = (int)((v - lo) * scale);
        bin = min(max(bin, 0), QBINS - 1);
        if (bin == t) {
            int idx = atomicAdd(&s_cnt, 1);
            if (idx < QCAP) cand[idx] = v;
        } else if (bin > t) {
            atomicMin(&s_minAbove, f2key(v));
        }
    }
    __syncthreads();
    int m = min(s_cnt, QCAP);
    for (int i = tid; i < QCAP; i += nt)
        if (i >= m) cand[i] = -__int_as_float(0x7f800000);
    __syncthreads();

    for (int kk = 2; kk <= QCAP; kk <<= 1) {
        for (int jj = kk >> 1; jj > 0; jj >>= 1) {
            for (int i = tid; i < QCAP; i += nt) {
                int ixj = i ^ jj;
                if (ixj > i) {
                    float a = cand[i], c = cand[ixj];
                    bool up = ((i & kk) == 0);
                    if (up ? (a < c) : (a > c)) { cand[i] = c; cand[ixj] = a; }
                }
            }
            __syncthreads();
        }
    }

    if (tid == 0) {
        int R1 = s_rankAbove;
        float v1000 = (R1 >= 1000) ? key2f(s_minAbove) : cand[999 - R1];
        float v1001 = cand[1000 - R1];
        float qq = __fmul_rn(0.95f, (float)(PP - 1));
        float fl = floorf(qq);
        float w_hi = __fadd_rn(qq, -fl);
        float w_lo = __fadd_rn(fl + 1.0f, -qq);
        float thr = __fadd_rn(__fmul_rn(v1001, w_lo), __fmul_rn(v1000, w_hi));
        g_thr[b] = thr;
    }
}

// ---------------- 4) threshold + ragged segment max (unchanged, R5) ----------
__global__ __launch_bounds__(256) void segmax_kernel(float* __restrict__ out) {
    __shared__ unsigned int keys[8 * CC];
    int b0 = blockIdx.x * 8;
    int tid = threadIdx.x;
    for (int i = tid; i < 8 * CC; i += 256) keys[i] = 0u;  // key(0.0f) floor
    __syncthreads();

    float th[8];
#pragma unroll
    for (int cc = 0; cc < 8; ++cc) th[cc] = g_thr[b0 + cc];

    for (int p = tid; p < PP; p += 256) {
        int c = g_seg32[p];
#pragma unroll
        for (int cc = 0; cc < 8; ++cc) {
            float v = g_xT[(size_t)(b0 + cc) * PP + p];
            v = (v < th[cc]) ? 0.0f : v;
            atomicMax(&keys[cc * CC + c], f2key(v));
        }
    }
    __syncthreads();

    for (int i = tid; i < 8 * CC; i += 256) {
        int c = i >> 3, cc = i & 7;
        out[(size_t)c * BB + b0 + cc] = key2f(keys[cc * CC + c]);
    }
}

// ---------------- launch ----------------
extern "C" void kernel_launch(void* const* d_in, const int* in_sizes, int n_in,
                              void* d_out, int out_size) {
    const float* data = nullptr;
    const float* w1 = nullptr;
    const void* segs = nullptr;
    for (int i = 0; i < n_in; ++i) {
        long long sz = in_sizes[i];
        if (sz == (long long)BB * DD) data = (const float*)d_in[i];
        else if (sz == (long long)PP * DD) w1 = (const float*)d_in[i];
        else if (sz == (long long)PP) segs = d_in[i];
    }
    if (!data) data = (const float*)d_in[0];
    if (!w1) w1 = (const float*)d_in[1];
    if (!segs) segs = d_in[2];
    float* out = (float*)d_out;

    float* gA; cudaGetSymbolAddress((void**)&gA, g_Af);
    float* gB; cudaGetSymbolAddress((void**)&gB, g_Bf);

    norm_split_kernel<<<BB, 128>>>(data, gA, (size_t)BB * DD, BB);
    norm_split_kernel<<<PPAD, 128>>>(w1, gB, (size_t)PPAD * DD, PP);
    seg_cast_kernel<<<(PP + 255) / 256, 256>>>(segs);

    cudaFuncSetAttribute(tc_gemm_kernel,
                         cudaFuncAttributeMaxDynamicSharedMemorySize, GSMEM);
    tc_gemm_kernel<<<dim3(MTILES, NTILES), 256, GSMEM>>>();

    cudaFuncSetAttribute(quantile_kernel,
                         cudaFuncAttributeMaxDynamicSharedMemorySize, QSMEM);
    quantile_kernel<<<BB, 512, QSMEM>>>();

    segmax_kernel<<<BB / 8, 256>>>(out);
}